// round 14
// baseline (speedup 1.0000x reference)
#include <cuda_runtime.h>
#include <cuda_fp16.h>
#include <cstdint>
#include <math.h>

#define DIM   768
#define HID   3072
#define HID2  1536
#define NLEV  9
#define SEQ   2048
#define MROWS 4096
#define EPSLN 1e-5f

#define BM 128
#define BN 96
#define BK 32
#define NT 384
#define MAX_TILES 48

#define ASTRH 40    /* A smem row stride in halves (80B): 16B aligned, 8-row bank-bijective */
#define BSTRH 104   /* B smem row stride in halves (208B): 96 data + 8 pad */
#define ABUFH (BM*ASTRH)   /* 5120 halves */
#define BBUFH (BK*BSTRH)   /* 3328 halves */
#define STAGEH (ABUFH+BBUFH)          /* 8448 halves = 16896 B */
#define NSTAGE 3
#define SMEM_BYTES (NSTAGE*STAGEH*2)  /* 50688 B */

#define NMAIN (HID/BN)    /* 32 */
#define NDIM  (DIM/BN)    /* 8 */
#define NH2   (HID2/BN)   /* 16 */
#define MID_MAIN_BLKS (NDIM*32)   /* 256 */
#define MID_BLKS (MID_MAIN_BLKS + NH2*MAX_TILES)

// gemm1 grid: 1024 GEMM tiles + 3840 weight-convert blocks
#define GEMM1_BLKS (NMAIN*(MROWS/BM))        /* 1024 */
#define N4_W  (DIM*HID/4)                    /* 589824 */
#define N4_A  (NLEV*DIM*HID2/4)              /* 2654208 */
#define REST_F4 (N4_W + 2*N4_A)              /* 5898240 = 3840*1536 */
#define CONV_PER_BLK (NT*4)                  /* 1536 */
#define NCONV (REST_F4/CONV_PER_BLK)         /* 3840 */
#define GEMM1_GRID (GEMM1_BLKS + NCONV)

// prep grid: W1 convert + 1 schedule + LN rows
#define NB_W1CONV ((N4_W + 1023)/1024)       /* 576 blocks, 4 f4/thread @256thr */
#define NB_PREP_ALL (NB_W1CONV + 1 + MROWS)

// ---------------- scratch (no allocations allowed) ----------------
__device__ __half g_xnorm[MROWS*DIM];
__device__ __half g_h[(size_t)MROWS*HID];
__device__ float  g_main[MROWS*DIM];
__device__ __half g_hl[MROWS*HID2];
__device__ __half g_W1h[DIM*HID];
__device__ __half g_W2h[HID*DIM];
__device__ __half g_A1h[NLEV*DIM*HID2];
__device__ __half g_A2h[NLEV*HID2*DIM];
__device__ float g_mix[SEQ];
__device__ int   g_depth[SEQ];
__device__ int   g_rowperm[MROWS];
__device__ int   g_sched_lvl[MAX_TILES];
__device__ int   g_sched_start[MAX_TILES];
__device__ int   g_sched_rows[MAX_TILES];
__device__ int   g_ntiles;

// ---------------- PTX helpers ----------------
__device__ __forceinline__ uint32_t smem_u32(const void* p) {
    return (uint32_t)__cvta_generic_to_shared(p);
}
__device__ __forceinline__ void cp16(uint32_t dst, const void* src) {
    asm volatile("cp.async.cg.shared.global [%0], [%1], 16;" :: "r"(dst), "l"(src));
}
__device__ __forceinline__ void cp_commit() {
    asm volatile("cp.async.commit_group;" ::: "memory");
}
__device__ __forceinline__ void cp_wait1() {
    asm volatile("cp.async.wait_group 1;" ::: "memory");
}
__device__ __forceinline__ void ldsm_x4(uint32_t& r0, uint32_t& r1, uint32_t& r2, uint32_t& r3,
                                        uint32_t addr) {
    asm volatile("ldmatrix.sync.aligned.m8n8.x4.shared.b16 {%0,%1,%2,%3}, [%4];"
                 : "=r"(r0), "=r"(r1), "=r"(r2), "=r"(r3) : "r"(addr));
}
__device__ __forceinline__ void ldsm_x4_t(uint32_t& r0, uint32_t& r1, uint32_t& r2, uint32_t& r3,
                                          uint32_t addr) {
    asm volatile("ldmatrix.sync.aligned.m8n8.x4.trans.shared.b16 {%0,%1,%2,%3}, [%4];"
                 : "=r"(r0), "=r"(r1), "=r"(r2), "=r"(r3) : "r"(addr));
}
__device__ __forceinline__ void mma_fp16(float& c0, float& c1, float& c2, float& c3,
                                         uint32_t a0, uint32_t a1, uint32_t a2, uint32_t a3,
                                         uint32_t b0, uint32_t b1) {
    asm volatile(
        "mma.sync.aligned.m16n8k16.row.col.f32.f16.f16.f32 "
        "{%0,%1,%2,%3}, {%4,%5,%6,%7}, {%8,%9}, {%0,%1,%2,%3};"
        : "+f"(c0), "+f"(c1), "+f"(c2), "+f"(c3)
        : "r"(a0), "r"(a1), "r"(a2), "r"(a3), "r"(b0), "r"(b1));
}
__device__ __forceinline__ void cvt_f4_to_h4(const float4* src, __half* dst) {
    float4 v = *src;
    __half2 lo = __floats2half2_rn(v.x, v.y);
    __half2 hi = __floats2half2_rn(v.z, v.w);
    uint2 pk = make_uint2(*(uint32_t*)&lo, *(uint32_t*)&hi);
    *(uint2*)dst = pk;
}

// ---------------- prep: W1 convert + schedule + layernorm ----------------
__global__ void __launch_bounds__(256) k_prep_all(
        const float4* __restrict__ W1,
        const int* __restrict__ levels, const float* __restrict__ lmw,
        const float* __restrict__ x, const float* __restrict__ gamma,
        const float* __restrict__ beta) {
    int b = blockIdx.x;
    int t = threadIdx.x;
    if (b < NB_W1CONV) {
#pragma unroll
        for (int j = 0; j < 4; ++j) {
            int i = b*1024 + t + j*256;
            if (i < N4_W) cvt_f4_to_h4(W1 + i, g_W1h + 4*(size_t)i);
        }
    } else if (b == NB_W1CONV) {
        __shared__ int cnt[NLEV];
        __shared__ int cursor[NLEV];
        __shared__ float denom_sh;
        if (t < NLEV) cnt[t] = 0;
        __syncthreads();
        for (int s = t; s < SEQ; s += 256) {
            int d = levels[s*4];
            d = min(max(d, 0), NLEV-1);
            g_depth[s] = d;
            atomicAdd(&cnt[d], 1);
        }
        __syncthreads();
        if (t == 0) {
            int o = 0, tile = 0;
            float denom = 0.f;
            for (int l = 0; l < NLEV; ++l) {
                cursor[l] = o;
                int rows = 2*cnt[l];
                int nt2 = (rows + BM - 1)/BM;
                for (int i = 0; i < nt2 && tile < MAX_TILES; ++i) {
                    g_sched_lvl[tile]   = l;
                    g_sched_start[tile] = o + i*BM;
                    g_sched_rows[tile]  = min(BM, rows - i*BM);
                    ++tile;
                }
                o += rows;
                denom += (float)cnt[l] * expf(lmw[l]);
            }
            for (int i = tile; i < MAX_TILES; ++i) g_sched_rows[i] = 0;
            g_ntiles = tile;
            denom_sh = denom;
        }
        __syncthreads();
        for (int r = t; r < MROWS; r += 256) {
            int s = r & (SEQ-1);
            int d = g_depth[s];
            int pos = atomicAdd(&cursor[d], 1);
            g_rowperm[pos] = r;
        }
        float denom = denom_sh;
        for (int s = t; s < SEQ; s += 256)
            g_mix[s] = expf(lmw[g_depth[s]]) / denom;
    } else {
        int row = b - NB_W1CONV - 1;
        const float* xr = x + (size_t)row*DIM;
        float v0 = xr[t], v1 = xr[t+256], v2 = xr[t+512];
        float s  = v0+v1+v2;
        float sq = v0*v0 + v1*v1 + v2*v2;
        __shared__ float red0[8], red1[8], mv[2];
#pragma unroll
        for (int o = 16; o > 0; o >>= 1) {
            s  += __shfl_xor_sync(0xffffffffu, s,  o);
            sq += __shfl_xor_sync(0xffffffffu, sq, o);
        }
        int wid = t >> 5, lid = t & 31;
        if (lid == 0) { red0[wid] = s; red1[wid] = sq; }
        __syncthreads();
        if (t == 0) {
            float S = 0.f, SQ = 0.f;
#pragma unroll
            for (int i = 0; i < 8; ++i) { S += red0[i]; SQ += red1[i]; }
            float mean = S * (1.0f/DIM);
            float var  = SQ * (1.0f/DIM) - mean*mean;
            mv[0] = mean; mv[1] = rsqrtf(var + EPSLN);
        }
        __syncthreads();
        float mean = mv[0], inv = mv[1];
        __half* o = g_xnorm + (size_t)row*DIM;
        o[t]     = __float2half_rn((v0-mean)*inv*gamma[t]     + beta[t]);
        o[t+256] = __float2half_rn((v1-mean)*inv*gamma[t+256] + beta[t+256]);
        o[t+512] = __float2half_rn((v2-mean)*inv*gamma[t+512] + beta[t+512]);
    }
}

// ---------------- chunk loader: A 128 rows (gathered) x 32 halves; B 32 x 96 halves ----------------
__device__ __forceinline__ void load_chunk(const __half* __restrict__ A, int lda,
                                           const __half* __restrict__ B, int ldb,
                                           int n0, int k0,
                                           const int* __restrict__ rowidx,
                                           __half* As, __half* Bs) {
    int t = threadIdx.x;
#pragma unroll
    for (int i = 0; i < 2; ++i) {
        int ci = t + i*NT;
        if (ci < 512) {
            int row = ci >> 2, seg = ci & 3;
            cp16(smem_u32(As + row*ASTRH + seg*8),
                 A + (size_t)rowidx[row]*lda + k0 + seg*8);
        }
    }
    {
        int k = t / 12, c16 = t % 12;
        cp16(smem_u32(Bs + k*BSTRH + c16*8),
             B + (size_t)(k0+k)*ldb + n0 + c16*8);
    }
}

// ---------------- mma mainloop: 3-stage ring; 12 warps 4(M)x3(N); fp16 m16n8k16 ----------------
__device__ __forceinline__ void mma_mainloop(const __half* __restrict__ A, int lda,
                                             const __half* __restrict__ B, int ldb,
                                             int K, int n0,
                                             const int* __restrict__ rowidx,
                                             __half* smem, float acc[2][4][4]) {
    int t = threadIdx.x;
    int wid = t >> 5, lane = t & 31;
    int wm = wid & 3, wnn = wid >> 2;
    int l8 = lane & 7, lhi = (lane >> 3) & 1, lch = lane >> 4;

    uint32_t a_off[2];
#pragma unroll
    for (int mt = 0; mt < 2; ++mt) {
        int row = wm*32 + mt*16 + lhi*8 + l8;
        a_off[mt] = (uint32_t)((row*ASTRH + lch*8) * 2);
    }
    uint32_t b_off[2];
#pragma unroll
    for (int np = 0; np < 2; ++np) {
        int k = lhi*8 + l8;
        int n = wnn*32 + np*16 + lch*8;
        b_off[np] = (uint32_t)(ABUFH*2 + (k*BSTRH + n) * 2);
    }

    int nch = K / BK;
    load_chunk(A, lda, B, ldb, n0, 0,  rowidx, smem,            smem + ABUFH);
    cp_commit();
    load_chunk(A, lda, B, ldb, n0, BK, rowidx, smem + STAGEH,   smem + STAGEH + ABUFH);
    cp_commit();

    for (int c = 0; c < nch; ++c) {
        cp_wait1();
        __syncthreads();
        uint32_t st_base = smem_u32(smem + (c % NSTAGE)*STAGEH);
#pragma unroll
        for (int ks = 0; ks < 2; ++ks) {
            uint32_t af[2][4], bf[4][2];
#pragma unroll
            for (int mt = 0; mt < 2; ++mt)
                ldsm_x4(af[mt][0], af[mt][1], af[mt][2], af[mt][3],
                        st_base + a_off[mt] + (uint32_t)(ks*32));
#pragma unroll
            for (int np = 0; np < 2; ++np)
                ldsm_x4_t(bf[2*np][0], bf[2*np][1], bf[2*np+1][0], bf[2*np+1][1],
                          st_base + b_off[np] + (uint32_t)(ks*16*BSTRH*2));
#pragma unroll
            for (int mt = 0; mt < 2; ++mt)
#pragma unroll
                for (int nt = 0; nt < 4; ++nt)
                    mma_fp16(acc[mt][nt][0], acc[mt][nt][1],
                             acc[mt][nt][2], acc[mt][nt][3],
                             af[mt][0], af[mt][1], af[mt][2], af[mt][3],
                             bf[nt][0], bf[nt][1]);
        }
        if (c + 2 < nch) {
            int st = (c + 2) % NSTAGE;
            load_chunk(A, lda, B, ldb, n0, (c+2)*BK, rowidx,
                       smem + st*STAGEH, smem + st*STAGEH + ABUFH);
        }
        cp_commit();
    }
}

__device__ __forceinline__ float gelu_exact(float v) {
    return 0.5f * v * (1.0f + erff(v * 0.70710678118654752f));
}
__device__ __forceinline__ void st_h2(__half* p, float a, float b) {
    *(__half2*)p = __floats2half2_rn(a, b);
}

// ---------------- gemm1 + embedded weight conversion (W2/A1/A2) ----------------
__global__ void __launch_bounds__(NT, 2) k_gemm1_main(const float* __restrict__ b1,
                                                      const float4* __restrict__ W2,
                                                      const float4* __restrict__ A1,
                                                      const float4* __restrict__ A2) {
    int bid = blockIdx.x;
    int t = threadIdx.x;
    if (bid >= GEMM1_BLKS) {
        // ---- convert W2/A1/A2 to fp16 while GEMM tiles run ----
        int base = (bid - GEMM1_BLKS)*CONV_PER_BLK + t;
#pragma unroll
        for (int j = 0; j < 4; ++j) {
            int i = base + j*NT;
            if (i < N4_W)
                cvt_f4_to_h4(W2 + i, g_W2h + 4*(size_t)i);
            else if (i < N4_W + N4_A)
                cvt_f4_to_h4(A1 + (i - N4_W), g_A1h + 4*(size_t)(i - N4_W));
            else
                cvt_f4_to_h4(A2 + (i - N4_W - N4_A), g_A2h + 4*(size_t)(i - N4_W - N4_A));
        }
        return;
    }
    extern __shared__ __half smem[];
    __shared__ int s_row[BM];
    int m0 = (bid / NMAIN) * BM, n0 = (bid % NMAIN) * BN;
    if (t < BM) s_row[t] = m0 + t;
    __syncthreads();
    float acc[2][4][4] = {};
    mma_mainloop(g_xnorm, DIM, g_W1h, HID, DIM, n0, s_row, smem, acc);
    int wid = t >> 5, lane = t & 31;
    int wm = wid & 3, wnn = wid >> 2, qid = lane >> 2, qtr = lane & 3;
#pragma unroll
    for (int mt = 0; mt < 2; ++mt) {
        int r0 = m0 + wm*32 + mt*16 + qid;
#pragma unroll
        for (int nt = 0; nt < 4; ++nt) {
            int col = n0 + wnn*32 + nt*8 + qtr*2;
            float bx = b1[col], by = b1[col+1];
            st_h2(g_h + (size_t)r0*HID + col,
                  gelu_exact(acc[mt][nt][0]+bx), gelu_exact(acc[mt][nt][1]+by));
            st_h2(g_h + (size_t)(r0+8)*HID + col,
                  gelu_exact(acc[mt][nt][2]+bx), gelu_exact(acc[mt][nt][3]+by));
        }
    }
}

// ---------------- fused mid kernel: gemm2_main tiles + gemm1_adapt tiles ----------------
__global__ void __launch_bounds__(NT, 2) k_mid(const float* __restrict__ b2,
                                               const float* __restrict__ a1b) {
    extern __shared__ __half smem[];
    __shared__ int s_row[BM];
    int t = threadIdx.x;
    int bid = blockIdx.x;
    int wid = t >> 5, lane = t & 31;
    int wm = wid & 3, wnn = wid >> 2, qid = lane >> 2, qtr = lane & 3;

    if (bid < MID_MAIN_BLKS) {
        int m0 = (bid / NDIM) * BM, n0 = (bid % NDIM) * BN;
        if (t < BM) s_row[t] = m0 + t;
        __syncthreads();
        float acc[2][4][4] = {};
        mma_mainloop(g_h, HID, g_W2h, DIM, HID, n0, s_row, smem, acc);
#pragma unroll
        for (int mt = 0; mt < 2; ++mt) {
            int r0 = m0 + wm*32 + mt*16 + qid;
#pragma unroll
            for (int nt = 0; nt < 4; ++nt) {
                int col = n0 + wnn*32 + nt*8 + qtr*2;
                float bx = b2[col], by = b2[col+1];
                *(float2*)(g_main + (size_t)r0*DIM + col) =
                    make_float2(acc[mt][nt][0]+bx, acc[mt][nt][1]+by);
                *(float2*)(g_main + (size_t)(r0+8)*DIM + col) =
                    make_float2(acc[mt][nt][2]+bx, acc[mt][nt][3]+by);
            }
        }
    } else {
        int b2i = bid - MID_MAIN_BLKS;
        int tile = b2i / NH2;
        if (tile >= g_ntiles) return;
        int n0 = (b2i % NH2) * BN;
        int lvl = g_sched_lvl[tile], start = g_sched_start[tile], rows = g_sched_rows[tile];
        if (t < BM) s_row[t] = g_rowperm[start + min(t, rows-1)];
        __syncthreads();
        float acc[2][4][4] = {};
        mma_mainloop(g_xnorm, DIM, g_A1h + (size_t)lvl*DIM*HID2, HID2, DIM, n0,
                     s_row, smem, acc);
        const float* bb = a1b + (size_t)lvl*HID2;
#pragma unroll
        for (int mt = 0; mt < 2; ++mt) {
            int ml = wm*32 + mt*16 + qid;
#pragma unroll
            for (int nt = 0; nt < 4; ++nt) {
                int col = n0 + wnn*32 + nt*8 + qtr*2;
                float bx = bb[col], by = bb[col+1];
                if (ml < rows)
                    st_h2(g_hl + (size_t)(start+ml)*HID2 + col,
                          fmaxf(acc[mt][nt][0]+bx, 0.f), fmaxf(acc[mt][nt][1]+by, 0.f));
                if (ml+8 < rows)
                    st_h2(g_hl + (size_t)(start+ml+8)*HID2 + col,
                          fmaxf(acc[mt][nt][2]+bx, 0.f), fmaxf(acc[mt][nt][3]+by, 0.f));
            }
        }
    }
}

// ---------------- adapter GEMM2 + final combine ----------------
__global__ void __launch_bounds__(NT, 2) k_gemm2_adapt(const float* __restrict__ a2b,
                                                       float* __restrict__ out) {
    if ((int)blockIdx.y >= g_ntiles) return;
    extern __shared__ __half smem[];
    __shared__ int s_row[BM];
    int t = threadIdx.x;
    int tile = blockIdx.y;
    int lvl = g_sched_lvl[tile], start = g_sched_start[tile], rows = g_sched_rows[tile];
    int n0 = blockIdx.x * BN;
    if (t < BM) s_row[t] = min(start + t, MROWS-1);
    __syncthreads();
    float acc[2][4][4] = {};
    mma_mainloop(g_hl, HID2, g_A2h + (size_t)lvl*HID2*DIM, DIM, HID2, n0, s_row, smem, acc);
    int wid = t >> 5, lane = t & 31;
    int wm = wid & 3, wnn = wid >> 2, qid = lane >> 2, qtr = lane & 3;
    const float* bb = a2b + (size_t)lvl*DIM;
#pragma unroll
    for (int mt = 0; mt < 2; ++mt) {
        int ml = wm*32 + mt*16 + qid;
#pragma unroll
        for (int nt = 0; nt < 4; ++nt) {
            int col = n0 + wnn*32 + nt*8 + qtr*2;
            float bx = bb[col], by = bb[col+1];
            if (ml < rows) {
                int r = g_rowperm[start + ml];
                float mix = g_mix[r & (SEQ-1)];
                const float* mp = g_main + (size_t)r*DIM + col;
                *(float2*)(out + (size_t)r*DIM + col) =
                    make_float2(mp[0]*(1.f-mix) + (acc[mt][nt][0]+bx)*mix,
                                mp[1]*(1.f-mix) + (acc[mt][nt][1]+by)*mix);
            }
            if (ml+8 < rows) {
                int r = g_rowperm[start + ml + 8];
                float mix = g_mix[r & (SEQ-1)];
                const float* mp = g_main + (size_t)r*DIM + col;
                *(float2*)(out + (size_t)r*DIM + col) =
                    make_float2(mp[0]*(1.f-mix) + (acc[mt][nt][2]+bx)*mix,
                                mp[1]*(1.f-mix) + (acc[mt][nt][3]+by)*mix);
            }
        }
    }
}

// ---------------- launch ----------------
extern "C" void kernel_launch(void* const* d_in, const int* in_sizes, int n_in,
                              void* d_out, int out_size) {
    const float* x      = (const float*)d_in[0];
    const int*   levels = (const int*)  d_in[1];
    const float* gamma  = (const float*)d_in[2];
    const float* beta   = (const float*)d_in[3];
    const float* W1     = (const float*)d_in[4];
    const float* b1     = (const float*)d_in[5];
    const float* W2     = (const float*)d_in[6];
    const float* b2     = (const float*)d_in[7];
    const float* A1     = (const float*)d_in[8];
    const float* a1b    = (const float*)d_in[9];
    const float* A2     = (const float*)d_in[10];
    const float* a2b    = (const float*)d_in[11];
    const float* lmw    = (const float*)d_in[12];
    float* out = (float*)d_out;

    cudaFuncSetAttribute(k_gemm1_main,  cudaFuncAttributeMaxDynamicSharedMemorySize, SMEM_BYTES);
    cudaFuncSetAttribute(k_mid,         cudaFuncAttributeMaxDynamicSharedMemorySize, SMEM_BYTES);
    cudaFuncSetAttribute(k_gemm2_adapt, cudaFuncAttributeMaxDynamicSharedMemorySize, SMEM_BYTES);

    k_prep_all<<<NB_PREP_ALL, 256>>>((const float4*)W1, levels, lmw, x, gamma, beta);
    k_gemm1_main <<<GEMM1_GRID, NT, SMEM_BYTES>>>(b1, (const float4*)W2,
                                                  (const float4*)A1, (const float4*)A2);
    k_mid        <<<MID_BLKS, NT, SMEM_BYTES>>>(b2, a1b);
    k_gemm2_adapt<<<dim3(NDIM, MAX_TILES), NT, SMEM_BYTES>>>(a2b, out);
}

// round 15
// speedup vs baseline: 1.0008x; 1.0008x over previous
#include <cuda_runtime.h>
#include <cuda_fp16.h>
#include <cstdint>
#include <math.h>

#define DIM   768
#define HID   3072
#define HID2  1536
#define NLEV  9
#define SEQ   2048
#define MROWS 4096
#define EPSLN 1e-5f

#define BM 128
#define BN 96
#define BK 32
#define NT 384
#define MAX_TILES 48

#define ASTRH 40    /* A smem row stride in halves (80B) */
#define BSTRH 104   /* B smem row stride in halves (208B) */
#define ABUFH (BM*ASTRH)
#define BBUFH (BK*BSTRH)
#define STAGEH (ABUFH+BBUFH)
#define NSTAGE 3
#define SMEM_BYTES (NSTAGE*STAGEH*2)

#define NMAIN (HID/BN)    /* 32 */
#define NDIM  (DIM/BN)    /* 8 */
#define NH2   (HID2/BN)   /* 16 */

#define S1_G1_BLKS (NMAIN*(MROWS/BM))          /* 1024 gemm1 tiles */
#define S1_BLKS    (S1_G1_BLKS + NH2*MAX_TILES)/* +768 adapt1 */
#define S2_MAIN_BLKS (NDIM*(MROWS/BM))         /* 256 gemm2_main tiles */
#define S2_BLKS    (S2_MAIN_BLKS + NDIM*MAX_TILES) /* +384 adapt2 */

// ---------------- scratch (no allocations allowed) ----------------
__device__ __half g_xnorm[MROWS*DIM];
__device__ __half g_h[(size_t)MROWS*HID];
__device__ float  g_main[MROWS*DIM];
__device__ __half g_adapt[MROWS*DIM];
__device__ __half g_hl[MROWS*HID2];
__device__ __half g_W1h[DIM*HID];
__device__ __half g_W2h[HID*DIM];
__device__ __half g_A1h[NLEV*DIM*HID2];
__device__ __half g_A2h[NLEV*HID2*DIM];
__device__ float g_mix[SEQ];
__device__ int   g_depth[SEQ];
__device__ int   g_rowperm[MROWS];
__device__ int   g_sched_lvl[MAX_TILES];
__device__ int   g_sched_start[MAX_TILES];
__device__ int   g_sched_rows[MAX_TILES];
__device__ int   g_ntiles;

// ---------------- PTX helpers ----------------
__device__ __forceinline__ uint32_t smem_u32(const void* p) {
    return (uint32_t)__cvta_generic_to_shared(p);
}
__device__ __forceinline__ void cp16(uint32_t dst, const void* src) {
    asm volatile("cp.async.cg.shared.global [%0], [%1], 16;" :: "r"(dst), "l"(src));
}
__device__ __forceinline__ void cp_commit() {
    asm volatile("cp.async.commit_group;" ::: "memory");
}
__device__ __forceinline__ void cp_wait1() {
    asm volatile("cp.async.wait_group 1;" ::: "memory");
}
__device__ __forceinline__ void ldsm_x4(uint32_t& r0, uint32_t& r1, uint32_t& r2, uint32_t& r3,
                                        uint32_t addr) {
    asm volatile("ldmatrix.sync.aligned.m8n8.x4.shared.b16 {%0,%1,%2,%3}, [%4];"
                 : "=r"(r0), "=r"(r1), "=r"(r2), "=r"(r3) : "r"(addr));
}
__device__ __forceinline__ void ldsm_x4_t(uint32_t& r0, uint32_t& r1, uint32_t& r2, uint32_t& r3,
                                          uint32_t addr) {
    asm volatile("ldmatrix.sync.aligned.m8n8.x4.trans.shared.b16 {%0,%1,%2,%3}, [%4];"
                 : "=r"(r0), "=r"(r1), "=r"(r2), "=r"(r3) : "r"(addr));
}
__device__ __forceinline__ void mma_fp16(float& c0, float& c1, float& c2, float& c3,
                                         uint32_t a0, uint32_t a1, uint32_t a2, uint32_t a3,
                                         uint32_t b0, uint32_t b1) {
    asm volatile(
        "mma.sync.aligned.m16n8k16.row.col.f32.f16.f16.f32 "
        "{%0,%1,%2,%3}, {%4,%5,%6,%7}, {%8,%9}, {%0,%1,%2,%3};"
        : "+f"(c0), "+f"(c1), "+f"(c2), "+f"(c3)
        : "r"(a0), "r"(a1), "r"(a2), "r"(a3), "r"(b0), "r"(b1));
}
__device__ __forceinline__ void cvt_f4_to_h4(const float4* src, __half* dst) {
    float4 v = *src;
    __half2 lo = __floats2half2_rn(v.x, v.y);
    __half2 hi = __floats2half2_rn(v.z, v.w);
    uint2 pk = make_uint2(*(uint32_t*)&lo, *(uint32_t*)&hi);
    *(uint2*)dst = pk;
}

// ---------------- fused prep: all-weights fp16 convert + schedule + layernorm ----------------
#define N4_W (DIM*HID/4)
#define N4_A (NLEV*DIM*HID2/4)
#define N4_TOTAL (2*N4_W + 2*N4_A)
#define NB_ROUND ((N4_TOTAL+255)/256)
#define NB_PREP_ALL (NB_ROUND + 1 + MROWS)

__global__ void __launch_bounds__(256) k_prep_all(
        const float4* __restrict__ W1, const float4* __restrict__ W2,
        const float4* __restrict__ A1, const float4* __restrict__ A2,
        const int* __restrict__ levels, const float* __restrict__ lmw,
        const float* __restrict__ x, const float* __restrict__ gamma,
        const float* __restrict__ beta) {
    int b = blockIdx.x;
    int t = threadIdx.x;
    if (b < NB_ROUND) {
        int i = b*256 + t;
        if (i >= N4_TOTAL) return;
        const float4* src; __half* dst;
        if (i < N4_W)            { src = W1 + i;                 dst = g_W1h + 4*(size_t)i; }
        else if (i < 2*N4_W)     { src = W2 + (i - N4_W);        dst = g_W2h + 4*(size_t)(i - N4_W); }
        else if (i < 2*N4_W+N4_A){ src = A1 + (i - 2*N4_W);      dst = g_A1h + 4*(size_t)(i - 2*N4_W); }
        else                     { src = A2 + (i - 2*N4_W-N4_A); dst = g_A2h + 4*(size_t)(i - 2*N4_W-N4_A); }
        cvt_f4_to_h4(src, dst);
    } else if (b == NB_ROUND) {
        __shared__ int cnt[NLEV];
        __shared__ int cursor[NLEV];
        __shared__ float denom_sh;
        if (t < NLEV) cnt[t] = 0;
        __syncthreads();
        for (int s = t; s < SEQ; s += 256) {
            int d = levels[s*4];
            d = min(max(d, 0), NLEV-1);
            g_depth[s] = d;
            atomicAdd(&cnt[d], 1);
        }
        __syncthreads();
        if (t == 0) {
            int o = 0, tile = 0;
            float denom = 0.f;
            for (int l = 0; l < NLEV; ++l) {
                cursor[l] = o;
                int rows = 2*cnt[l];
                int nt2 = (rows + BM - 1)/BM;
                for (int i = 0; i < nt2 && tile < MAX_TILES; ++i) {
                    g_sched_lvl[tile]   = l;
                    g_sched_start[tile] = o + i*BM;
                    g_sched_rows[tile]  = min(BM, rows - i*BM);
                    ++tile;
                }
                o += rows;
                denom += (float)cnt[l] * expf(lmw[l]);
            }
            for (int i = tile; i < MAX_TILES; ++i) g_sched_rows[i] = 0;
            g_ntiles = tile;
            denom_sh = denom;
        }
        __syncthreads();
        for (int r = t; r < MROWS; r += 256) {
            int s = r & (SEQ-1);
            int d = g_depth[s];
            int pos = atomicAdd(&cursor[d], 1);
            g_rowperm[pos] = r;
        }
        float denom = denom_sh;
        for (int s = t; s < SEQ; s += 256)
            g_mix[s] = expf(lmw[g_depth[s]]) / denom;
    } else {
        int row = b - NB_ROUND - 1;
        const float* xr = x + (size_t)row*DIM;
        float v0 = xr[t], v1 = xr[t+256], v2 = xr[t+512];
        float s  = v0+v1+v2;
        float sq = v0*v0 + v1*v1 + v2*v2;
        __shared__ float red0[8], red1[8], mv[2];
#pragma unroll
        for (int o = 16; o > 0; o >>= 1) {
            s  += __shfl_xor_sync(0xffffffffu, s,  o);
            sq += __shfl_xor_sync(0xffffffffu, sq, o);
        }
        int wid = t >> 5, lid = t & 31;
        if (lid == 0) { red0[wid] = s; red1[wid] = sq; }
        __syncthreads();
        if (t == 0) {
            float S = 0.f, SQ = 0.f;
#pragma unroll
            for (int i = 0; i < 8; ++i) { S += red0[i]; SQ += red1[i]; }
            float mean = S * (1.0f/DIM);
            float var  = SQ * (1.0f/DIM) - mean*mean;
            mv[0] = mean; mv[1] = rsqrtf(var + EPSLN);
        }
        __syncthreads();
        float mean = mv[0], inv = mv[1];
        __half* o = g_xnorm + (size_t)row*DIM;
        o[t]     = __float2half_rn((v0-mean)*inv*gamma[t]     + beta[t]);
        o[t+256] = __float2half_rn((v1-mean)*inv*gamma[t+256] + beta[t+256]);
        o[t+512] = __float2half_rn((v2-mean)*inv*gamma[t+512] + beta[t+512]);
    }
}

// ---------------- chunk loader ----------------
__device__ __forceinline__ void load_chunk(const __half* __restrict__ A, int lda,
                                           const __half* __restrict__ B, int ldb,
                                           int n0, int k0,
                                           const int* __restrict__ rowidx,
                                           __half* As, __half* Bs) {
    int t = threadIdx.x;
#pragma unroll
    for (int i = 0; i < 2; ++i) {
        int ci = t + i*NT;
        if (ci < 512) {
            int row = ci >> 2, seg = ci & 3;
            cp16(smem_u32(As + row*ASTRH + seg*8),
                 A + (size_t)rowidx[row]*lda + k0 + seg*8);
        }
    }
    {
        int k = t / 12, c16 = t % 12;
        cp16(smem_u32(Bs + k*BSTRH + c16*8),
             B + (size_t)(k0+k)*ldb + n0 + c16*8);
    }
}

// ---------------- mma mainloop: 3-stage ring; 12 warps 4(M)x3(N); fp16 m16n8k16 ----------------
__device__ __forceinline__ void mma_mainloop(const __half* __restrict__ A, int lda,
                                             const __half* __restrict__ B, int ldb,
                                             int K, int n0,
                                             const int* __restrict__ rowidx,
                                             __half* smem, float acc[2][4][4]) {
    int t = threadIdx.x;
    int wid = t >> 5, lane = t & 31;
    int wm = wid & 3, wnn = wid >> 2;
    int l8 = lane & 7, lhi = (lane >> 3) & 1, lch = lane >> 4;

    uint32_t a_off[2];
#pragma unroll
    for (int mt = 0; mt < 2; ++mt) {
        int row = wm*32 + mt*16 + lhi*8 + l8;
        a_off[mt] = (uint32_t)((row*ASTRH + lch*8) * 2);
    }
    uint32_t b_off[2];
#pragma unroll
    for (int np = 0; np < 2; ++np) {
        int k = lhi*8 + l8;
        int n = wnn*32 + np*16 + lch*8;
        b_off[np] = (uint32_t)(ABUFH*2 + (k*BSTRH + n) * 2);
    }

    int nch = K / BK;
    load_chunk(A, lda, B, ldb, n0, 0,  rowidx, smem,            smem + ABUFH);
    cp_commit();
    load_chunk(A, lda, B, ldb, n0, BK, rowidx, smem + STAGEH,   smem + STAGEH + ABUFH);
    cp_commit();

    for (int c = 0; c < nch; ++c) {
        cp_wait1();
        __syncthreads();
        uint32_t st_base = smem_u32(smem + (c % NSTAGE)*STAGEH);
#pragma unroll
        for (int ks = 0; ks < 2; ++ks) {
            uint32_t af[2][4], bf[4][2];
#pragma unroll
            for (int mt = 0; mt < 2; ++mt)
                ldsm_x4(af[mt][0], af[mt][1], af[mt][2], af[mt][3],
                        st_base + a_off[mt] + (uint32_t)(ks*32));
#pragma unroll
            for (int np = 0; np < 2; ++np)
                ldsm_x4_t(bf[2*np][0], bf[2*np][1], bf[2*np+1][0], bf[2*np+1][1],
                          st_base + b_off[np] + (uint32_t)(ks*16*BSTRH*2));
#pragma unroll
            for (int mt = 0; mt < 2; ++mt)
#pragma unroll
                for (int nt = 0; nt < 4; ++nt)
                    mma_fp16(acc[mt][nt][0], acc[mt][nt][1],
                             acc[mt][nt][2], acc[mt][nt][3],
                             af[mt][0], af[mt][1], af[mt][2], af[mt][3],
                             bf[nt][0], bf[nt][1]);
        }
        if (c + 2 < nch) {
            int st = (c + 2) % NSTAGE;
            load_chunk(A, lda, B, ldb, n0, (c+2)*BK, rowidx,
                       smem + st*STAGEH, smem + st*STAGEH + ABUFH);
        }
        cp_commit();
    }
}

__device__ __forceinline__ float gelu_exact(float v) {
    return 0.5f * v * (1.0f + erff(v * 0.70710678118654752f));
}
__device__ __forceinline__ void st_h2(__half* p, float a, float b) {
    *(__half2*)p = __floats2half2_rn(a, b);
}

// ---------------- stage 1: gemm1_main tiles + adapt1 tiles (both depend only on prep) ----------------
__global__ void __launch_bounds__(NT, 2) k_stage1(const float* __restrict__ b1,
                                                  const float* __restrict__ a1b) {
    extern __shared__ __half smem[];
    __shared__ int s_row[BM];
    int t = threadIdx.x;
    int bid = blockIdx.x;
    int wid = t >> 5, lane = t & 31;
    int wm = wid & 3, wnn = wid >> 2, qid = lane >> 2, qtr = lane & 3;

    if (bid < S1_G1_BLKS) {
        // ---- h = fp16(gelu(xnorm @ W1 + b1)) ----
        int m0 = (bid / NMAIN) * BM, n0 = (bid % NMAIN) * BN;
        if (t < BM) s_row[t] = m0 + t;
        __syncthreads();
        float acc[2][4][4] = {};
        mma_mainloop(g_xnorm, DIM, g_W1h, HID, DIM, n0, s_row, smem, acc);
#pragma unroll
        for (int mt = 0; mt < 2; ++mt) {
            int r0 = m0 + wm*32 + mt*16 + qid;
#pragma unroll
            for (int nt = 0; nt < 4; ++nt) {
                int col = n0 + wnn*32 + nt*8 + qtr*2;
                float bx = b1[col], by = b1[col+1];
                st_h2(g_h + (size_t)r0*HID + col,
                      gelu_exact(acc[mt][nt][0]+bx), gelu_exact(acc[mt][nt][1]+by));
                st_h2(g_h + (size_t)(r0+8)*HID + col,
                      gelu_exact(acc[mt][nt][2]+bx), gelu_exact(acc[mt][nt][3]+by));
            }
        }
    } else {
        // ---- hl = fp16(relu(xnorm[perm] @ A1[lvl] + a1b[lvl])) ----
        int b2i = bid - S1_G1_BLKS;
        int tile = b2i / NH2;
        if (tile >= g_ntiles) return;
        int n0 = (b2i % NH2) * BN;
        int lvl = g_sched_lvl[tile], start = g_sched_start[tile], rows = g_sched_rows[tile];
        if (t < BM) s_row[t] = g_rowperm[start + min(t, rows-1)];
        __syncthreads();
        float acc[2][4][4] = {};
        mma_mainloop(g_xnorm, DIM, g_A1h + (size_t)lvl*DIM*HID2, HID2, DIM, n0,
                     s_row, smem, acc);
        const float* bb = a1b + (size_t)lvl*HID2;
#pragma unroll
        for (int mt = 0; mt < 2; ++mt) {
            int ml = wm*32 + mt*16 + qid;
#pragma unroll
            for (int nt = 0; nt < 4; ++nt) {
                int col = n0 + wnn*32 + nt*8 + qtr*2;
                float bx = bb[col], by = bb[col+1];
                if (ml < rows)
                    st_h2(g_hl + (size_t)(start+ml)*HID2 + col,
                          fmaxf(acc[mt][nt][0]+bx, 0.f), fmaxf(acc[mt][nt][1]+by, 0.f));
                if (ml+8 < rows)
                    st_h2(g_hl + (size_t)(start+ml+8)*HID2 + col,
                          fmaxf(acc[mt][nt][2]+bx, 0.f), fmaxf(acc[mt][nt][3]+by, 0.f));
            }
        }
    }
}

// ---------------- stage 2: gemm2_main tiles + adapt2 tiles (adapt writes g_adapt) ----------------
__global__ void __launch_bounds__(NT, 2) k_stage2(const float* __restrict__ b2,
                                                  const float* __restrict__ a2b) {
    extern __shared__ __half smem[];
    __shared__ int s_row[BM];
    int t = threadIdx.x;
    int bid = blockIdx.x;
    int wid = t >> 5, lane = t & 31;
    int wm = wid & 3, wnn = wid >> 2, qid = lane >> 2, qtr = lane & 3;

    if (bid < S2_MAIN_BLKS) {
        // ---- main = g_h @ W2 + b2 (fp32) ----
        int m0 = (bid / NDIM) * BM, n0 = (bid % NDIM) * BN;
        if (t < BM) s_row[t] = m0 + t;
        __syncthreads();
        float acc[2][4][4] = {};
        mma_mainloop(g_h, HID, g_W2h, DIM, HID, n0, s_row, smem, acc);
#pragma unroll
        for (int mt = 0; mt < 2; ++mt) {
            int r0 = m0 + wm*32 + mt*16 + qid;
#pragma unroll
            for (int nt = 0; nt < 4; ++nt) {
                int col = n0 + wnn*32 + nt*8 + qtr*2;
                float bx = b2[col], by = b2[col+1];
                *(float2*)(g_main + (size_t)r0*DIM + col) =
                    make_float2(acc[mt][nt][0]+bx, acc[mt][nt][1]+by);
                *(float2*)(g_main + (size_t)(r0+8)*DIM + col) =
                    make_float2(acc[mt][nt][2]+bx, acc[mt][nt][3]+by);
            }
        }
    } else {
        // ---- adapt[r] = fp16(hl[perm] @ A2[lvl] + a2b[lvl]) ----
        int b2i = bid - S2_MAIN_BLKS;
        int tile = b2i / NDIM;
        if (tile >= g_ntiles) return;
        int n0 = (b2i % NDIM) * BN;
        int lvl = g_sched_lvl[tile], start = g_sched_start[tile], rows = g_sched_rows[tile];
        if (t < BM) s_row[t] = min(start + t, MROWS-1);   // g_hl rows are compacted
        __syncthreads();
        float acc[2][4][4] = {};
        mma_mainloop(g_hl, HID2, g_A2h + (size_t)lvl*HID2*DIM, DIM, HID2, n0,
                     s_row, smem, acc);
        const float* bb = a2b + (size_t)lvl*DIM;
#pragma unroll
        for (int mt = 0; mt < 2; ++mt) {
            int ml = wm*32 + mt*16 + qid;
#pragma unroll
            for (int nt = 0; nt < 4; ++nt) {
                int col = n0 + wnn*32 + nt*8 + qtr*2;
                float bx = bb[col], by = bb[col+1];
                if (ml < rows) {
                    int r = g_rowperm[start + ml];
                    st_h2(g_adapt + (size_t)r*DIM + col,
                          acc[mt][nt][0]+bx, acc[mt][nt][1]+by);
                }
                if (ml+8 < rows) {
                    int r = g_rowperm[start + ml + 8];
                    st_h2(g_adapt + (size_t)r*DIM + col,
                          acc[mt][nt][2]+bx, acc[mt][nt][3]+by);
                }
            }
        }
    }
}

// ---------------- final combine: out = main*(1-mix) + adapt*mix ----------------
#define COMB_ELEMS (MROWS*DIM/2)
__global__ void __launch_bounds__(256) k_combine(float* __restrict__ out) {
    int i = blockIdx.x*256 + threadIdx.x;
    if (i >= COMB_ELEMS) return;
    int r = i / (DIM/2);
    float mix = g_mix[r & (SEQ-1)];
    float2 mn = *(const float2*)(g_main + 2*(size_t)i);
    __half2 ad = *(const __half2*)(g_adapt + 2*(size_t)i);
    float2 adf = __half22float2(ad);
    *(float2*)(out + 2*(size_t)i) =
        make_float2(mn.x*(1.f-mix) + adf.x*mix, mn.y*(1.f-mix) + adf.y*mix);
}

// ---------------- launch ----------------
extern "C" void kernel_launch(void* const* d_in, const int* in_sizes, int n_in,
                              void* d_out, int out_size) {
    const float* x      = (const float*)d_in[0];
    const int*   levels = (const int*)  d_in[1];
    const float* gamma  = (const float*)d_in[2];
    const float* beta   = (const float*)d_in[3];
    const float* W1     = (const float*)d_in[4];
    const float* b1     = (const float*)d_in[5];
    const float* W2     = (const float*)d_in[6];
    const float* b2     = (const float*)d_in[7];
    const float* A1     = (const float*)d_in[8];
    const float* a1b    = (const float*)d_in[9];
    const float* A2     = (const float*)d_in[10];
    const float* a2b    = (const float*)d_in[11];
    const float* lmw    = (const float*)d_in[12];
    float* out = (float*)d_out;

    cudaFuncSetAttribute(k_stage1, cudaFuncAttributeMaxDynamicSharedMemorySize, SMEM_BYTES);
    cudaFuncSetAttribute(k_stage2, cudaFuncAttributeMaxDynamicSharedMemorySize, SMEM_BYTES);

    k_prep_all<<<NB_PREP_ALL, 256>>>((const float4*)W1, (const float4*)W2,
                                     (const float4*)A1, (const float4*)A2,
                                     levels, lmw, x, gamma, beta);
    k_stage1<<<S1_BLKS, NT, SMEM_BYTES>>>(b1, a1b);
    k_stage2<<<S2_BLKS, NT, SMEM_BYTES>>>(b2, a2b);
    k_combine<<<(COMB_ELEMS+255)/256, 256>>>(out);
}

// round 16
// speedup vs baseline: 1.1758x; 1.1749x over previous
#include <cuda_runtime.h>
#include <cuda_fp16.h>
#include <cstdint>
#include <math.h>

#define DIM   768
#define HID   3072
#define HID2  1536
#define NLEV  9
#define SEQ   2048
#define MROWS 4096
#define EPSLN 1e-5f

#define BM 128
#define BN 128
#define BK 64
#define NT 256
#define MAX_TILES 48

#define ASTRH 72    /* A smem row stride in halves (144B): 64 data + 8 pad */
#define BSTRH 136   /* B smem row stride in halves (272B): 128 data + 8 pad */
#define ABUFH (BM*ASTRH)   /* 9216 halves */
#define BBUFH (BK*BSTRH)   /* 8704 halves */
#define STAGEH (ABUFH+BBUFH)          /* 17920 halves = 35840 B */
#define NSTAGE 3
#define SMEM_BYTES (NSTAGE*STAGEH*2)  /* 107520 B */

#define NMAIN (HID/BN)    /* 24 */
#define NDIM  (DIM/BN)    /* 6 */
#define NH2   (HID2/BN)   /* 12 */
#define MID_MAIN_BLKS (NDIM*(MROWS/BM))    /* 192 */
#define MID_BLKS (MID_MAIN_BLKS + NH2*MAX_TILES)

// ---------------- scratch (no allocations allowed) ----------------
__device__ __half g_xnorm[MROWS*DIM];
__device__ __half g_h[(size_t)MROWS*HID];
__device__ float  g_main[MROWS*DIM];
__device__ __half g_hl[MROWS*HID2];
__device__ __half g_W1h[DIM*HID];
__device__ __half g_W2h[HID*DIM];
__device__ __half g_A1h[NLEV*DIM*HID2];
__device__ __half g_A2h[NLEV*HID2*DIM];
__device__ float g_mix[SEQ];
__device__ int   g_depth[SEQ];
__device__ int   g_rowperm[MROWS];
__device__ int   g_sched_lvl[MAX_TILES];
__device__ int   g_sched_start[MAX_TILES];
__device__ int   g_sched_rows[MAX_TILES];
__device__ int   g_ntiles;

// ---------------- PTX helpers ----------------
__device__ __forceinline__ uint32_t smem_u32(const void* p) {
    return (uint32_t)__cvta_generic_to_shared(p);
}
__device__ __forceinline__ void cp16(uint32_t dst, const void* src) {
    asm volatile("cp.async.cg.shared.global [%0], [%1], 16;" :: "r"(dst), "l"(src));
}
__device__ __forceinline__ void cp_commit() {
    asm volatile("cp.async.commit_group;" ::: "memory");
}
__device__ __forceinline__ void cp_wait1() {
    asm volatile("cp.async.wait_group 1;" ::: "memory");
}
__device__ __forceinline__ void ldsm_x4(uint32_t& r0, uint32_t& r1, uint32_t& r2, uint32_t& r3,
                                        uint32_t addr) {
    asm volatile("ldmatrix.sync.aligned.m8n8.x4.shared.b16 {%0,%1,%2,%3}, [%4];"
                 : "=r"(r0), "=r"(r1), "=r"(r2), "=r"(r3) : "r"(addr));
}
__device__ __forceinline__ void ldsm_x4_t(uint32_t& r0, uint32_t& r1, uint32_t& r2, uint32_t& r3,
                                          uint32_t addr) {
    asm volatile("ldmatrix.sync.aligned.m8n8.x4.trans.shared.b16 {%0,%1,%2,%3}, [%4];"
                 : "=r"(r0), "=r"(r1), "=r"(r2), "=r"(r3) : "r"(addr));
}
__device__ __forceinline__ void mma_fp16(float& c0, float& c1, float& c2, float& c3,
                                         uint32_t a0, uint32_t a1, uint32_t a2, uint32_t a3,
                                         uint32_t b0, uint32_t b1) {
    asm volatile(
        "mma.sync.aligned.m16n8k16.row.col.f32.f16.f16.f32 "
        "{%0,%1,%2,%3}, {%4,%5,%6,%7}, {%8,%9}, {%0,%1,%2,%3};"
        : "+f"(c0), "+f"(c1), "+f"(c2), "+f"(c3)
        : "r"(a0), "r"(a1), "r"(a2), "r"(a3), "r"(b0), "r"(b1));
}
__device__ __forceinline__ void cvt_f4_to_h4(const float4* src, __half* dst) {
    float4 v = *src;
    __half2 lo = __floats2half2_rn(v.x, v.y);
    __half2 hi = __floats2half2_rn(v.z, v.w);
    uint2 pk = make_uint2(*(uint32_t*)&lo, *(uint32_t*)&hi);
    *(uint2*)dst = pk;
}

// ---------------- fused prep: all-weights fp16 convert + schedule + layernorm ----------------
#define N4_W (DIM*HID/4)
#define N4_A (NLEV*DIM*HID2/4)
#define N4_TOTAL (2*N4_W + 2*N4_A)
#define NB_ROUND ((N4_TOTAL+255)/256)
#define NB_PREP_ALL (NB_ROUND + 1 + MROWS)

__global__ void __launch_bounds__(256) k_prep_all(
        const float4* __restrict__ W1, const float4* __restrict__ W2,
        const float4* __restrict__ A1, const float4* __restrict__ A2,
        const int* __restrict__ levels, const float* __restrict__ lmw,
        const float* __restrict__ x, const float* __restrict__ gamma,
        const float* __restrict__ beta) {
    int b = blockIdx.x;
    int t = threadIdx.x;
    if (b < NB_ROUND) {
        int i = b*256 + t;
        if (i >= N4_TOTAL) return;
        const float4* src; __half* dst;
        if (i < N4_W)            { src = W1 + i;                 dst = g_W1h + 4*(size_t)i; }
        else if (i < 2*N4_W)     { src = W2 + (i - N4_W);        dst = g_W2h + 4*(size_t)(i - N4_W); }
        else if (i < 2*N4_W+N4_A){ src = A1 + (i - 2*N4_W);      dst = g_A1h + 4*(size_t)(i - 2*N4_W); }
        else                     { src = A2 + (i - 2*N4_W-N4_A); dst = g_A2h + 4*(size_t)(i - 2*N4_W-N4_A); }
        cvt_f4_to_h4(src, dst);
    } else if (b == NB_ROUND) {
        __shared__ int cnt[NLEV];
        __shared__ int cursor[NLEV];
        __shared__ float denom_sh;
        if (t < NLEV) cnt[t] = 0;
        __syncthreads();
        for (int s = t; s < SEQ; s += 256) {
            int d = levels[s*4];
            d = min(max(d, 0), NLEV-1);
            g_depth[s] = d;
            atomicAdd(&cnt[d], 1);
        }
        __syncthreads();
        if (t == 0) {
            int o = 0, tile = 0;
            float denom = 0.f;
            for (int l = 0; l < NLEV; ++l) {
                cursor[l] = o;
                int rows = 2*cnt[l];
                int nt2 = (rows + BM - 1)/BM;
                for (int i = 0; i < nt2 && tile < MAX_TILES; ++i) {
                    g_sched_lvl[tile]   = l;
                    g_sched_start[tile] = o + i*BM;
                    g_sched_rows[tile]  = min(BM, rows - i*BM);
                    ++tile;
                }
                o += rows;
                denom += (float)cnt[l] * expf(lmw[l]);
            }
            for (int i = tile; i < MAX_TILES; ++i) g_sched_rows[i] = 0;
            g_ntiles = tile;
            denom_sh = denom;
        }
        __syncthreads();
        for (int r = t; r < MROWS; r += 256) {
            int s = r & (SEQ-1);
            int d = g_depth[s];
            int pos = atomicAdd(&cursor[d], 1);
            g_rowperm[pos] = r;
        }
        float denom = denom_sh;
        for (int s = t; s < SEQ; s += 256)
            g_mix[s] = expf(lmw[g_depth[s]]) / denom;
    } else {
        int row = b - NB_ROUND - 1;
        const float* xr = x + (size_t)row*DIM;
        float v0 = xr[t], v1 = xr[t+256], v2 = xr[t+512];
        float s  = v0+v1+v2;
        float sq = v0*v0 + v1*v1 + v2*v2;
        __shared__ float red0[8], red1[8], mv[2];
#pragma unroll
        for (int o = 16; o > 0; o >>= 1) {
            s  += __shfl_xor_sync(0xffffffffu, s,  o);
            sq += __shfl_xor_sync(0xffffffffu, sq, o);
        }
        int wid = t >> 5, lid = t & 31;
        if (lid == 0) { red0[wid] = s; red1[wid] = sq; }
        __syncthreads();
        if (t == 0) {
            float S = 0.f, SQ = 0.f;
#pragma unroll
            for (int i = 0; i < 8; ++i) { S += red0[i]; SQ += red1[i]; }
            float mean = S * (1.0f/DIM);
            float var  = SQ * (1.0f/DIM) - mean*mean;
            mv[0] = mean; mv[1] = rsqrtf(var + EPSLN);
        }
        __syncthreads();
        float mean = mv[0], inv = mv[1];
        __half* o = g_xnorm + (size_t)row*DIM;
        o[t]     = __float2half_rn((v0-mean)*inv*gamma[t]     + beta[t]);
        o[t+256] = __float2half_rn((v1-mean)*inv*gamma[t+256] + beta[t+256]);
        o[t+512] = __float2half_rn((v2-mean)*inv*gamma[t+512] + beta[t+512]);
    }
}

// ---------------- chunk loader: A 128 rows x 64 halves; B 64 rows x 128 halves; NT=256 ----------------
__device__ __forceinline__ void load_chunk(const __half* __restrict__ A, int lda,
                                           const __half* __restrict__ B, int ldb,
                                           int n0, int k0,
                                           const int* __restrict__ rowidx,
                                           __half* As, __half* Bs) {
    int t = threadIdx.x;
#pragma unroll
    for (int i = 0; i < 4; ++i) {                  // 1024 A cp16
        int ci = t + i*NT;
        int row = ci >> 3, seg = ci & 7;
        cp16(smem_u32(As + row*ASTRH + seg*8),
             A + (size_t)rowidx[row]*lda + k0 + seg*8);
    }
#pragma unroll
    for (int i = 0; i < 4; ++i) {                  // 1024 B cp16
        int ci = t + i*NT;
        int k = ci >> 4, c16 = ci & 15;
        cp16(smem_u32(Bs + k*BSTRH + c16*8),
             B + (size_t)(k0+k)*ldb + n0 + c16*8);
    }
}

// ---------------- mma mainloop: 3-stage ring; 8 warps 4(M)x2(N), 32x64 each; BK=64 ----------------
__device__ __forceinline__ void mma_mainloop(const __half* __restrict__ A, int lda,
                                             const __half* __restrict__ B, int ldb,
                                             int K, int n0,
                                             const int* __restrict__ rowidx,
                                             __half* smem, float acc[2][8][4]) {
    int t = threadIdx.x;
    int wid = t >> 5, lane = t & 31;
    int wm = wid & 3, wnn = wid >> 2;      // 4 M-warps x 2 N-warps
    int l8 = lane & 7, lhi = (lane >> 3) & 1, lch = lane >> 4;

    uint32_t a_off[2];
#pragma unroll
    for (int mt = 0; mt < 2; ++mt) {
        int row = wm*32 + mt*16 + lhi*8 + l8;
        a_off[mt] = (uint32_t)((row*ASTRH + lch*8) * 2);
    }
    uint32_t b_off[4];
#pragma unroll
    for (int np = 0; np < 4; ++np) {
        int k = lhi*8 + l8;
        int n = wnn*64 + np*16 + lch*8;
        b_off[np] = (uint32_t)(ABUFH*2 + (k*BSTRH + n) * 2);
    }

    int nch = K / BK;
    load_chunk(A, lda, B, ldb, n0, 0,  rowidx, smem,            smem + ABUFH);
    cp_commit();
    load_chunk(A, lda, B, ldb, n0, BK, rowidx, smem + STAGEH,   smem + STAGEH + ABUFH);
    cp_commit();

    for (int c = 0; c < nch; ++c) {
        cp_wait1();
        __syncthreads();
        uint32_t st_base = smem_u32(smem + (c % NSTAGE)*STAGEH);
#pragma unroll
        for (int ks = 0; ks < 4; ++ks) {           // 4 k-steps of 16
            uint32_t af[2][4], bf[8][2];
#pragma unroll
            for (int mt = 0; mt < 2; ++mt)
                ldsm_x4(af[mt][0], af[mt][1], af[mt][2], af[mt][3],
                        st_base + a_off[mt] + (uint32_t)(ks*32));       // 16 halves = 32B
#pragma unroll
            for (int np = 0; np < 4; ++np)
                ldsm_x4_t(bf[2*np][0], bf[2*np][1], bf[2*np+1][0], bf[2*np+1][1],
                          st_base + b_off[np] + (uint32_t)(ks*16*BSTRH*2));
#pragma unroll
            for (int mt = 0; mt < 2; ++mt)
#pragma unroll
                for (int nt = 0; nt < 8; ++nt)
                    mma_fp16(acc[mt][nt][0], acc[mt][nt][1],
                             acc[mt][nt][2], acc[mt][nt][3],
                             af[mt][0], af[mt][1], af[mt][2], af[mt][3],
                             bf[nt][0], bf[nt][1]);
        }
        if (c + 2 < nch) {
            int st = (c + 2) % NSTAGE;
            load_chunk(A, lda, B, ldb, n0, (c+2)*BK, rowidx,
                       smem + st*STAGEH, smem + st*STAGEH + ABUFH);
        }
        cp_commit();
    }
}

__device__ __forceinline__ float gelu_exact(float v) {
    return 0.5f * v * (1.0f + erff(v * 0.70710678118654752f));
}
__device__ __forceinline__ void st_h2(__half* p, float a, float b) {
    *(__half2*)p = __floats2half2_rn(a, b);
}

// ---------------- main MLP GEMM1: h = fp16(gelu(xnorm @ W1 + b1)) ----------------
__global__ void __launch_bounds__(NT, 2) k_gemm1_main(const float* __restrict__ b1) {
    extern __shared__ __half smem[];
    __shared__ int s_row[BM];
    int t = threadIdx.x;
    int m0 = blockIdx.y * BM, n0 = blockIdx.x * BN;
    if (t < BM) s_row[t] = m0 + t;
    __syncthreads();
    float acc[2][8][4] = {};
    mma_mainloop(g_xnorm, DIM, g_W1h, HID, DIM, n0, s_row, smem, acc);
    int wid = t >> 5, lane = t & 31;
    int wm = wid & 3, wnn = wid >> 2, qid = lane >> 2, qtr = lane & 3;
#pragma unroll
    for (int mt = 0; mt < 2; ++mt) {
        int r0 = m0 + wm*32 + mt*16 + qid;
#pragma unroll
        for (int nt = 0; nt < 8; ++nt) {
            int col = n0 + wnn*64 + nt*8 + qtr*2;
            float bx = b1[col], by = b1[col+1];
            st_h2(g_h + (size_t)r0*HID + col,
                  gelu_exact(acc[mt][nt][0]+bx), gelu_exact(acc[mt][nt][1]+by));
            st_h2(g_h + (size_t)(r0+8)*HID + col,
                  gelu_exact(acc[mt][nt][2]+bx), gelu_exact(acc[mt][nt][3]+by));
        }
    }
}

// ---------------- fused mid kernel: gemm2_main tiles + gemm1_adapt tiles ----------------
__global__ void __launch_bounds__(NT, 2) k_mid(const float* __restrict__ b2,
                                               const float* __restrict__ a1b) {
    extern __shared__ __half smem[];
    __shared__ int s_row[BM];
    int t = threadIdx.x;
    int bid = blockIdx.x;
    int wid = t >> 5, lane = t & 31;
    int wm = wid & 3, wnn = wid >> 2, qid = lane >> 2, qtr = lane & 3;

    if (bid < MID_MAIN_BLKS) {
        // ---- main = g_h @ W2 + b2 (fp32 out) ----
        int m0 = (bid / NDIM) * BM, n0 = (bid % NDIM) * BN;
        if (t < BM) s_row[t] = m0 + t;
        __syncthreads();
        float acc[2][8][4] = {};
        mma_mainloop(g_h, HID, g_W2h, DIM, HID, n0, s_row, smem, acc);
#pragma unroll
        for (int mt = 0; mt < 2; ++mt) {
            int r0 = m0 + wm*32 + mt*16 + qid;
#pragma unroll
            for (int nt = 0; nt < 8; ++nt) {
                int col = n0 + wnn*64 + nt*8 + qtr*2;
                float bx = b2[col], by = b2[col+1];
                *(float2*)(g_main + (size_t)r0*DIM + col) =
                    make_float2(acc[mt][nt][0]+bx, acc[mt][nt][1]+by);
                *(float2*)(g_main + (size_t)(r0+8)*DIM + col) =
                    make_float2(acc[mt][nt][2]+bx, acc[mt][nt][3]+by);
            }
        }
    } else {
        // ---- hl = fp16(relu(xnorm[perm] @ A1[lvl] + a1b[lvl])) ----
        int b2i = bid - MID_MAIN_BLKS;
        int tile = b2i / NH2;
        if (tile >= g_ntiles) return;
        int n0 = (b2i % NH2) * BN;
        int lvl = g_sched_lvl[tile], start = g_sched_start[tile], rows = g_sched_rows[tile];
        if (t < BM) s_row[t] = g_rowperm[start + min(t, rows-1)];
        __syncthreads();
        float acc[2][8][4] = {};
        mma_mainloop(g_xnorm, DIM, g_A1h + (size_t)lvl*DIM*HID2, HID2, DIM, n0,
                     s_row, smem, acc);
        const float* bb = a1b + (size_t)lvl*HID2;
#pragma unroll
        for (int mt = 0; mt < 2; ++mt) {
            int ml = wm*32 + mt*16 + qid;
#pragma unroll
            for (int nt = 0; nt < 8; ++nt) {
                int col = n0 + wnn*64 + nt*8 + qtr*2;
                float bx = bb[col], by = bb[col+1];
                if (ml < rows)
                    st_h2(g_hl + (size_t)(start+ml)*HID2 + col,
                          fmaxf(acc[mt][nt][0]+bx, 0.f), fmaxf(acc[mt][nt][1]+by, 0.f));
                if (ml+8 < rows)
                    st_h2(g_hl + (size_t)(start+ml+8)*HID2 + col,
                          fmaxf(acc[mt][nt][2]+bx, 0.f), fmaxf(acc[mt][nt][3]+by, 0.f));
            }
        }
    }
}

// ---------------- adapter GEMM2 + final combine ----------------
__global__ void __launch_bounds__(NT, 2) k_gemm2_adapt(const float* __restrict__ a2b,
                                                       float* __restrict__ out) {
    if ((int)blockIdx.y >= g_ntiles) return;
    extern __shared__ __half smem[];
    __shared__ int s_row[BM];
    int t = threadIdx.x;
    int tile = blockIdx.y;
    int lvl = g_sched_lvl[tile], start = g_sched_start[tile], rows = g_sched_rows[tile];
    int n0 = blockIdx.x * BN;
    if (t < BM) s_row[t] = min(start + t, MROWS-1);   // g_hl rows are compacted
    __syncthreads();
    float acc[2][8][4] = {};
    mma_mainloop(g_hl, HID2, g_A2h + (size_t)lvl*HID2*DIM, DIM, HID2, n0, s_row, smem, acc);
    int wid = t >> 5, lane = t & 31;
    int wm = wid & 3, wnn = wid >> 2, qid = lane >> 2, qtr = lane & 3;
    const float* bb = a2b + (size_t)lvl*DIM;
#pragma unroll
    for (int mt = 0; mt < 2; ++mt) {
        int ml = wm*32 + mt*16 + qid;
#pragma unroll
        for (int nt = 0; nt < 8; ++nt) {
            int col = n0 + wnn*64 + nt*8 + qtr*2;
            float bx = bb[col], by = bb[col+1];
            if (ml < rows) {
                int r = g_rowperm[start + ml];
                float mix = g_mix[r & (SEQ-1)];
                const float* mp = g_main + (size_t)r*DIM + col;
                *(float2*)(out + (size_t)r*DIM + col) =
                    make_float2(mp[0]*(1.f-mix) + (acc[mt][nt][0]+bx)*mix,
                                mp[1]*(1.f-mix) + (acc[mt][nt][1]+by)*mix);
            }
            if (ml+8 < rows) {
                int r = g_rowperm[start + ml + 8];
                float mix = g_mix[r & (SEQ-1)];
                const float* mp = g_main + (size_t)r*DIM + col;
                *(float2*)(out + (size_t)r*DIM + col) =
                    make_float2(mp[0]*(1.f-mix) + (acc[mt][nt][2]+bx)*mix,
                                mp[1]*(1.f-mix) + (acc[mt][nt][3]+by)*mix);
            }
        }
    }
}

// ---------------- launch ----------------
extern "C" void kernel_launch(void* const* d_in, const int* in_sizes, int n_in,
                              void* d_out, int out_size) {
    const float* x      = (const float*)d_in[0];
    const int*   levels = (const int*)  d_in[1];
    const float* gamma  = (const float*)d_in[2];
    const float* beta   = (const float*)d_in[3];
    const float* W1     = (const float*)d_in[4];
    const float* b1     = (const float*)d_in[5];
    const float* W2     = (const float*)d_in[6];
    const float* b2     = (const float*)d_in[7];
    const float* A1     = (const float*)d_in[8];
    const float* a1b    = (const float*)d_in[9];
    const float* A2     = (const float*)d_in[10];
    const float* a2b    = (const float*)d_in[11];
    const float* lmw    = (const float*)d_in[12];
    float* out = (float*)d_out;

    cudaFuncSetAttribute(k_gemm1_main,  cudaFuncAttributeMaxDynamicSharedMemorySize, SMEM_BYTES);
    cudaFuncSetAttribute(k_mid,         cudaFuncAttributeMaxDynamicSharedMemorySize, SMEM_BYTES);
    cudaFuncSetAttribute(k_gemm2_adapt, cudaFuncAttributeMaxDynamicSharedMemorySize, SMEM_BYTES);

    k_prep_all<<<NB_PREP_ALL, 256>>>((const float4*)W1, (const float4*)W2,
                                     (const float4*)A1, (const float4*)A2,
                                     levels, lmw, x, gamma, beta);
    k_gemm1_main <<<dim3(NMAIN, MROWS/BM), NT, SMEM_BYTES>>>(b1);
    k_mid        <<<MID_BLKS, NT, SMEM_BYTES>>>(b2, a1b);
    k_gemm2_adapt<<<dim3(NDIM, MAX_TILES), NT, SMEM_BYTES>>>(a2b, out);
}

// round 17
// speedup vs baseline: 1.1874x; 1.0098x over previous
#include <cuda_runtime.h>
#include <cuda_fp16.h>
#include <cstdint>
#include <math.h>

#define DIM   768
#define HID   3072
#define HID2  1536
#define NLEV  9
#define SEQ   2048
#define MROWS 4096
#define EPSLN 1e-5f

#define BM 128
#define BN 128
#define BK 64
#define NT 256
#define MAX_TILES 48

#define ASTRH 72    /* A smem row stride in halves (144B): 64 data + 8 pad */
#define BSTRH 136   /* B smem row stride in halves (272B): 128 data + 8 pad */
#define ABUFH (BM*ASTRH)   /* 9216 halves */
#define BBUFH (BK*BSTRH)   /* 8704 halves */
#define STAGEH (ABUFH+BBUFH)          /* 17920 halves = 35840 B */
#define NSTAGE 3
#define SMEM_BYTES (NSTAGE*STAGEH*2)  /* 107520 B */

/* adapt2: 64-row tiles */
#define A2BUFH (64*ASTRH)             /* 4608 halves */
#define A2STAGEH (A2BUFH+BBUFH)       /* 13312 halves = 26624 B */
#define A2SMEM_BYTES (NSTAGE*A2STAGEH*2)  /* 79872 B */

#define NMAIN (HID/BN)    /* 24 */
#define NDIM  (DIM/BN)    /* 6 */
#define NH2   (HID2/BN)   /* 12 */
#define MID_MAIN_BLKS (NDIM*(MROWS/BM))    /* 192 */
#define MID_BLKS (MID_MAIN_BLKS + NH2*MAX_TILES)

// ---------------- scratch (no allocations allowed) ----------------
__device__ __half g_xnorm[MROWS*DIM];
__device__ __half g_h[(size_t)MROWS*HID];
__device__ float  g_main[MROWS*DIM];
__device__ __half g_hl[MROWS*HID2];
__device__ __half g_W1h[DIM*HID];
__device__ __half g_W2h[HID*DIM];
__device__ __half g_A1h[NLEV*DIM*HID2];
__device__ __half g_A2h[NLEV*HID2*DIM];
__device__ float g_mix[SEQ];
__device__ int   g_depth[SEQ];
__device__ int   g_rowperm[MROWS];
__device__ int   g_sched_lvl[MAX_TILES];
__device__ int   g_sched_start[MAX_TILES];
__device__ int   g_sched_rows[MAX_TILES];
__device__ int   g_ntiles;

// ---------------- PTX helpers ----------------
__device__ __forceinline__ uint32_t smem_u32(const void* p) {
    return (uint32_t)__cvta_generic_to_shared(p);
}
__device__ __forceinline__ void cp16(uint32_t dst, const void* src) {
    asm volatile("cp.async.cg.shared.global [%0], [%1], 16;" :: "r"(dst), "l"(src));
}
__device__ __forceinline__ void cp_commit() {
    asm volatile("cp.async.commit_group;" ::: "memory");
}
__device__ __forceinline__ void cp_wait1() {
    asm volatile("cp.async.wait_group 1;" ::: "memory");
}
__device__ __forceinline__ void ldsm_x4(uint32_t& r0, uint32_t& r1, uint32_t& r2, uint32_t& r3,
                                        uint32_t addr) {
    asm volatile("ldmatrix.sync.aligned.m8n8.x4.shared.b16 {%0,%1,%2,%3}, [%4];"
                 : "=r"(r0), "=r"(r1), "=r"(r2), "=r"(r3) : "r"(addr));
}
__device__ __forceinline__ void ldsm_x4_t(uint32_t& r0, uint32_t& r1, uint32_t& r2, uint32_t& r3,
                                          uint32_t addr) {
    asm volatile("ldmatrix.sync.aligned.m8n8.x4.trans.shared.b16 {%0,%1,%2,%3}, [%4];"
                 : "=r"(r0), "=r"(r1), "=r"(r2), "=r"(r3) : "r"(addr));
}
__device__ __forceinline__ void mma_fp16(float& c0, float& c1, float& c2, float& c3,
                                         uint32_t a0, uint32_t a1, uint32_t a2, uint32_t a3,
                                         uint32_t b0, uint32_t b1) {
    asm volatile(
        "mma.sync.aligned.m16n8k16.row.col.f32.f16.f16.f32 "
        "{%0,%1,%2,%3}, {%4,%5,%6,%7}, {%8,%9}, {%0,%1,%2,%3};"
        : "+f"(c0), "+f"(c1), "+f"(c2), "+f"(c3)
        : "r"(a0), "r"(a1), "r"(a2), "r"(a3), "r"(b0), "r"(b1));
}
__device__ __forceinline__ void cvt_f4_to_h4(const float4* src, __half* dst) {
    float4 v = *src;
    __half2 lo = __floats2half2_rn(v.x, v.y);
    __half2 hi = __floats2half2_rn(v.z, v.w);
    uint2 pk = make_uint2(*(uint32_t*)&lo, *(uint32_t*)&hi);
    *(uint2*)dst = pk;
}

// ---------------- fused prep: all-weights fp16 convert + schedule + layernorm ----------------
#define N4_W (DIM*HID/4)
#define N4_A (NLEV*DIM*HID2/4)
#define N4_TOTAL (2*N4_W + 2*N4_A)
#define NB_ROUND ((N4_TOTAL+255)/256)
#define NB_PREP_ALL (NB_ROUND + 1 + MROWS)

__global__ void __launch_bounds__(256) k_prep_all(
        const float4* __restrict__ W1, const float4* __restrict__ W2,
        const float4* __restrict__ A1, const float4* __restrict__ A2,
        const int* __restrict__ levels, const float* __restrict__ lmw,
        const float* __restrict__ x, const float* __restrict__ gamma,
        const float* __restrict__ beta) {
    int b = blockIdx.x;
    int t = threadIdx.x;
    if (b < NB_ROUND) {
        int i = b*256 + t;
        if (i >= N4_TOTAL) return;
        const float4* src; __half* dst;
        if (i < N4_W)            { src = W1 + i;                 dst = g_W1h + 4*(size_t)i; }
        else if (i < 2*N4_W)     { src = W2 + (i - N4_W);        dst = g_W2h + 4*(size_t)(i - N4_W); }
        else if (i < 2*N4_W+N4_A){ src = A1 + (i - 2*N4_W);      dst = g_A1h + 4*(size_t)(i - 2*N4_W); }
        else                     { src = A2 + (i - 2*N4_W-N4_A); dst = g_A2h + 4*(size_t)(i - 2*N4_W-N4_A); }
        cvt_f4_to_h4(src, dst);
    } else if (b == NB_ROUND) {
        __shared__ int cnt[NLEV];
        __shared__ int cursor[NLEV];
        __shared__ float denom_sh;
        if (t < NLEV) cnt[t] = 0;
        __syncthreads();
        for (int s = t; s < SEQ; s += 256) {
            int d = levels[s*4];
            d = min(max(d, 0), NLEV-1);
            g_depth[s] = d;
            atomicAdd(&cnt[d], 1);
        }
        __syncthreads();
        if (t == 0) {
            int o = 0, tile = 0;
            float denom = 0.f;
            for (int l = 0; l < NLEV; ++l) {
                cursor[l] = o;
                int rows = 2*cnt[l];
                int nt2 = (rows + BM - 1)/BM;
                for (int i = 0; i < nt2 && tile < MAX_TILES; ++i) {
                    g_sched_lvl[tile]   = l;
                    g_sched_start[tile] = o + i*BM;
                    g_sched_rows[tile]  = min(BM, rows - i*BM);
                    ++tile;
                }
                o += rows;
                denom += (float)cnt[l] * expf(lmw[l]);
            }
            for (int i = tile; i < MAX_TILES; ++i) g_sched_rows[i] = 0;
            g_ntiles = tile;
            denom_sh = denom;
        }
        __syncthreads();
        for (int r = t; r < MROWS; r += 256) {
            int s = r & (SEQ-1);
            int d = g_depth[s];
            int pos = atomicAdd(&cursor[d], 1);
            g_rowperm[pos] = r;
        }
        float denom = denom_sh;
        for (int s = t; s < SEQ; s += 256)
            g_mix[s] = expf(lmw[g_depth[s]]) / denom;
    } else {
        int row = b - NB_ROUND - 1;
        const float* xr = x + (size_t)row*DIM;
        float v0 = xr[t], v1 = xr[t+256], v2 = xr[t+512];
        float s  = v0+v1+v2;
        float sq = v0*v0 + v1*v1 + v2*v2;
        __shared__ float red0[8], red1[8], mv[2];
#pragma unroll
        for (int o = 16; o > 0; o >>= 1) {
            s  += __shfl_xor_sync(0xffffffffu, s,  o);
            sq += __shfl_xor_sync(0xffffffffu, sq, o);
        }
        int wid = t >> 5, lid = t & 31;
        if (lid == 0) { red0[wid] = s; red1[wid] = sq; }
        __syncthreads();
        if (t == 0) {
            float S = 0.f, SQ = 0.f;
#pragma unroll
            for (int i = 0; i < 8; ++i) { S += red0[i]; SQ += red1[i]; }
            float mean = S * (1.0f/DIM);
            float var  = SQ * (1.0f/DIM) - mean*mean;
            mv[0] = mean; mv[1] = rsqrtf(var + EPSLN);
        }
        __syncthreads();
        float mean = mv[0], inv = mv[1];
        __half* o = g_xnorm + (size_t)row*DIM;
        o[t]     = __float2half_rn((v0-mean)*inv*gamma[t]     + beta[t]);
        o[t+256] = __float2half_rn((v1-mean)*inv*gamma[t+256] + beta[t+256]);
        o[t+512] = __float2half_rn((v2-mean)*inv*gamma[t+512] + beta[t+512]);
    }
}

// ---------------- chunk loader: A 128 rows x 64 halves; B 64 rows x 128 halves ----------------
__device__ __forceinline__ void load_chunk(const __half* __restrict__ A, int lda,
                                           const __half* __restrict__ B, int ldb,
                                           int n0, int k0,
                                           const int* __restrict__ rowidx,
                                           __half* As, __half* Bs) {
    int t = threadIdx.x;
#pragma unroll
    for (int i = 0; i < 4; ++i) {
        int ci = t + i*NT;
        int row = ci >> 3, seg = ci & 7;
        cp16(smem_u32(As + row*ASTRH + seg*8),
             A + (size_t)rowidx[row]*lda + k0 + seg*8);
    }
#pragma unroll
    for (int i = 0; i < 4; ++i) {
        int ci = t + i*NT;
        int k = ci >> 4, c16 = ci & 15;
        cp16(smem_u32(Bs + k*BSTRH + c16*8),
             B + (size_t)(k0+k)*ldb + n0 + c16*8);
    }
}

// ---------------- mma mainloop: 8 warps 4(M)x2(N), 32x64 each; BK=64 ----------------
__device__ __forceinline__ void mma_mainloop(const __half* __restrict__ A, int lda,
                                             const __half* __restrict__ B, int ldb,
                                             int K, int n0,
                                             const int* __restrict__ rowidx,
                                             __half* smem, float acc[2][8][4]) {
    int t = threadIdx.x;
    int wid = t >> 5, lane = t & 31;
    int wm = wid & 3, wnn = wid >> 2;
    int l8 = lane & 7, lhi = (lane >> 3) & 1, lch = lane >> 4;

    uint32_t a_off[2];
#pragma unroll
    for (int mt = 0; mt < 2; ++mt) {
        int row = wm*32 + mt*16 + lhi*8 + l8;
        a_off[mt] = (uint32_t)((row*ASTRH + lch*8) * 2);
    }
    uint32_t b_off[4];
#pragma unroll
    for (int np = 0; np < 4; ++np) {
        int k = lhi*8 + l8;
        int n = wnn*64 + np*16 + lch*8;
        b_off[np] = (uint32_t)(ABUFH*2 + (k*BSTRH + n) * 2);
    }

    int nch = K / BK;
    load_chunk(A, lda, B, ldb, n0, 0,  rowidx, smem,            smem + ABUFH);
    cp_commit();
    load_chunk(A, lda, B, ldb, n0, BK, rowidx, smem + STAGEH,   smem + STAGEH + ABUFH);
    cp_commit();

    for (int c = 0; c < nch; ++c) {
        cp_wait1();
        __syncthreads();
        uint32_t st_base = smem_u32(smem + (c % NSTAGE)*STAGEH);
#pragma unroll
        for (int ks = 0; ks < 4; ++ks) {
            uint32_t af[2][4], bf[8][2];
#pragma unroll
            for (int mt = 0; mt < 2; ++mt)
                ldsm_x4(af[mt][0], af[mt][1], af[mt][2], af[mt][3],
                        st_base + a_off[mt] + (uint32_t)(ks*32));
#pragma unroll
            for (int np = 0; np < 4; ++np)
                ldsm_x4_t(bf[2*np][0], bf[2*np][1], bf[2*np+1][0], bf[2*np+1][1],
                          st_base + b_off[np] + (uint32_t)(ks*16*BSTRH*2));
#pragma unroll
            for (int mt = 0; mt < 2; ++mt)
#pragma unroll
                for (int nt = 0; nt < 8; ++nt)
                    mma_fp16(acc[mt][nt][0], acc[mt][nt][1],
                             acc[mt][nt][2], acc[mt][nt][3],
                             af[mt][0], af[mt][1], af[mt][2], af[mt][3],
                             bf[nt][0], bf[nt][1]);
        }
        if (c + 2 < nch) {
            int st = (c + 2) % NSTAGE;
            load_chunk(A, lda, B, ldb, n0, (c+2)*BK, rowidx,
                       smem + st*STAGEH, smem + st*STAGEH + ABUFH);
        }
        cp_commit();
    }
}

__device__ __forceinline__ float gelu_exact(float v) {
    return 0.5f * v * (1.0f + erff(v * 0.70710678118654752f));
}
__device__ __forceinline__ void st_h2(__half* p, float a, float b) {
    *(__half2*)p = __floats2half2_rn(a, b);
}

// ---------------- main MLP GEMM1: h = fp16(gelu(xnorm @ W1 + b1)) ----------------
__global__ void __launch_bounds__(NT, 2) k_gemm1_main(const float* __restrict__ b1) {
    extern __shared__ __half smem[];
    __shared__ int s_row[BM];
    int t = threadIdx.x;
    int m0 = blockIdx.y * BM, n0 = blockIdx.x * BN;
    if (t < BM) s_row[t] = m0 + t;
    __syncthreads();
    float acc[2][8][4] = {};
    mma_mainloop(g_xnorm, DIM, g_W1h, HID, DIM, n0, s_row, smem, acc);
    int wid = t >> 5, lane = t & 31;
    int wm = wid & 3, wnn = wid >> 2, qid = lane >> 2, qtr = lane & 3;
#pragma unroll
    for (int mt = 0; mt < 2; ++mt) {
        int r0 = m0 + wm*32 + mt*16 + qid;
#pragma unroll
        for (int nt = 0; nt < 8; ++nt) {
            int col = n0 + wnn*64 + nt*8 + qtr*2;
            float bx = b1[col], by = b1[col+1];
            st_h2(g_h + (size_t)r0*HID + col,
                  gelu_exact(acc[mt][nt][0]+bx), gelu_exact(acc[mt][nt][1]+by));
            st_h2(g_h + (size_t)(r0+8)*HID + col,
                  gelu_exact(acc[mt][nt][2]+bx), gelu_exact(acc[mt][nt][3]+by));
        }
    }
}

// ---------------- fused mid kernel: gemm2_main tiles + gemm1_adapt tiles ----------------
__global__ void __launch_bounds__(NT, 2) k_mid(const float* __restrict__ b2,
                                               const float* __restrict__ a1b) {
    extern __shared__ __half smem[];
    __shared__ int s_row[BM];
    int t = threadIdx.x;
    int bid = blockIdx.x;
    int wid = t >> 5, lane = t & 31;
    int wm = wid & 3, wnn = wid >> 2, qid = lane >> 2, qtr = lane & 3;

    if (bid < MID_MAIN_BLKS) {
        int m0 = (bid / NDIM) * BM, n0 = (bid % NDIM) * BN;
        if (t < BM) s_row[t] = m0 + t;
        __syncthreads();
        float acc[2][8][4] = {};
        mma_mainloop(g_h, HID, g_W2h, DIM, HID, n0, s_row, smem, acc);
#pragma unroll
        for (int mt = 0; mt < 2; ++mt) {
            int r0 = m0 + wm*32 + mt*16 + qid;
#pragma unroll
            for (int nt = 0; nt < 8; ++nt) {
                int col = n0 + wnn*64 + nt*8 + qtr*2;
                float bx = b2[col], by = b2[col+1];
                *(float2*)(g_main + (size_t)r0*DIM + col) =
                    make_float2(acc[mt][nt][0]+bx, acc[mt][nt][1]+by);
                *(float2*)(g_main + (size_t)(r0+8)*DIM + col) =
                    make_float2(acc[mt][nt][2]+bx, acc[mt][nt][3]+by);
            }
        }
    } else {
        int b2i = bid - MID_MAIN_BLKS;
        int tile = b2i / NH2;
        if (tile >= g_ntiles) return;
        int n0 = (b2i % NH2) * BN;
        int lvl = g_sched_lvl[tile], start = g_sched_start[tile], rows = g_sched_rows[tile];
        if (t < BM) s_row[t] = g_rowperm[start + min(t, rows-1)];
        __syncthreads();
        float acc[2][8][4] = {};
        mma_mainloop(g_xnorm, DIM, g_A1h + (size_t)lvl*DIM*HID2, HID2, DIM, n0,
                     s_row, smem, acc);
        const float* bb = a1b + (size_t)lvl*HID2;
#pragma unroll
        for (int mt = 0; mt < 2; ++mt) {
            int ml = wm*32 + mt*16 + qid;
#pragma unroll
            for (int nt = 0; nt < 8; ++nt) {
                int col = n0 + wnn*64 + nt*8 + qtr*2;
                float bx = bb[col], by = bb[col+1];
                if (ml < rows)
                    st_h2(g_hl + (size_t)(start+ml)*HID2 + col,
                          fmaxf(acc[mt][nt][0]+bx, 0.f), fmaxf(acc[mt][nt][1]+by, 0.f));
                if (ml+8 < rows)
                    st_h2(g_hl + (size_t)(start+ml+8)*HID2 + col,
                          fmaxf(acc[mt][nt][2]+bx, 0.f), fmaxf(acc[mt][nt][3]+by, 0.f));
            }
        }
    }
}

// ---------------- adapt2 (64-row tiles) + final combine ----------------
// 8 warps: 2(M)x4(N), each 32x32. A tile 64 rows.
__global__ void __launch_bounds__(NT, 2) k_gemm2_adapt(const float* __restrict__ a2b,
                                                       float* __restrict__ out) {
    int tile = blockIdx.y >> 1, half = blockIdx.y & 1;
    if (tile >= g_ntiles) return;
    int rows_full = g_sched_rows[tile];
    int rows = rows_full - half*64;
    if (rows <= 0) return;
    rows = min(rows, 64);
    int start = g_sched_start[tile] + half*64;
    int lvl = g_sched_lvl[tile];

    extern __shared__ __half smem[];
    __shared__ int s_row[64];
    int t = threadIdx.x;
    int n0 = blockIdx.x * BN;
    if (t < 64) s_row[t] = min(start + t, MROWS-1);   // g_hl rows are compacted
    __syncthreads();

    int wid = t >> 5, lane = t & 31;
    int wm = wid & 1, wnn = wid >> 1;     // 2 M-warps x 4 N-warps
    int l8 = lane & 7, lhi = (lane >> 3) & 1, lch = lane >> 4;
    int qid = lane >> 2, qtr = lane & 3;

    uint32_t a_off[2];
#pragma unroll
    for (int mt = 0; mt < 2; ++mt) {
        int row = wm*32 + mt*16 + lhi*8 + l8;
        a_off[mt] = (uint32_t)((row*ASTRH + lch*8) * 2);
    }
    uint32_t b_off[2];
#pragma unroll
    for (int np = 0; np < 2; ++np) {
        int k = lhi*8 + l8;
        int n = wnn*32 + np*16 + lch*8;
        b_off[np] = (uint32_t)(A2BUFH*2 + (k*BSTRH + n) * 2);
    }

    const __half* A = g_hl;
    const __half* B = g_A2h + (size_t)lvl*HID2*DIM;
    float acc[2][4][4] = {};

    // loader lambda-ish macro: A 64 rows x 8 segs = 512 cp16; B 64 x 16 = 1024 cp16
#define A2_LOAD(k0, As, Bs)                                                  \
    do {                                                                     \
        _Pragma("unroll")                                                    \
        for (int i = 0; i < 2; ++i) {                                        \
            int ci = t + i*NT;                                               \
            int row = ci >> 3, seg = ci & 7;                                 \
            cp16(smem_u32((As) + row*ASTRH + seg*8),                         \
                 A + (size_t)s_row[row]*HID2 + (k0) + seg*8);                \
        }                                                                    \
        _Pragma("unroll")                                                    \
        for (int i = 0; i < 4; ++i) {                                        \
            int ci = t + i*NT;                                               \
            int k = ci >> 4, c16 = ci & 15;                                  \
            cp16(smem_u32((Bs) + k*BSTRH + c16*8),                           \
                 B + (size_t)((k0)+k)*DIM + n0 + c16*8);                     \
        }                                                                    \
        cp_commit();                                                         \
    } while (0)

    const int nch = HID2 / BK;   /* 24 */
    A2_LOAD(0,  smem,            smem + A2BUFH);
    A2_LOAD(BK, smem + A2STAGEH, smem + A2STAGEH + A2BUFH);

    for (int c = 0; c < nch; ++c) {
        cp_wait1();
        __syncthreads();
        uint32_t st_base = smem_u32(smem + (c % NSTAGE)*A2STAGEH);
#pragma unroll
        for (int ks = 0; ks < 4; ++ks) {
            uint32_t af[2][4], bf[4][2];
#pragma unroll
            for (int mt = 0; mt < 2; ++mt)
                ldsm_x4(af[mt][0], af[mt][1], af[mt][2], af[mt][3],
                        st_base + a_off[mt] + (uint32_t)(ks*32));
#pragma unroll
            for (int np = 0; np < 2; ++np)
                ldsm_x4_t(bf[2*np][0], bf[2*np][1], bf[2*np+1][0], bf[2*np+1][1],
                          st_base + b_off[np] + (uint32_t)(ks*16*BSTRH*2));
#pragma unroll
            for (int mt = 0; mt < 2; ++mt)
#pragma unroll
                for (int nt = 0; nt < 4; ++nt)
                    mma_fp16(acc[mt][nt][0], acc[mt][nt][1],
                             acc[mt][nt][2], acc[mt][nt][3],
                             af[mt][0], af[mt][1], af[mt][2], af[mt][3],
                             bf[nt][0], bf[nt][1]);
        }
        if (c + 2 < nch) {
            int st = (c + 2) % NSTAGE;
            A2_LOAD((c+2)*BK, smem + st*A2STAGEH, smem + st*A2STAGEH + A2BUFH);
        } else {
            cp_commit();   // keep group count uniform at tail
        }
    }
#undef A2_LOAD

    const float* bb = a2b + (size_t)lvl*DIM;
#pragma unroll
    for (int mt = 0; mt < 2; ++mt) {
        int ml = wm*32 + mt*16 + qid;
#pragma unroll
        for (int nt = 0; nt < 4; ++nt) {
            int col = n0 + wnn*32 + nt*8 + qtr*2;
            float bx = bb[col], by = bb[col+1];
            if (ml < rows) {
                int r = g_rowperm[start + ml];
                float mix = g_mix[r & (SEQ-1)];
                const float* mp = g_main + (size_t)r*DIM + col;
                *(float2*)(out + (size_t)r*DIM + col) =
                    make_float2(mp[0]*(1.f-mix) + (acc[mt][nt][0]+bx)*mix,
                                mp[1]*(1.f-mix) + (acc[mt][nt][1]+by)*mix);
            }
            if (ml+8 < rows) {
                int r = g_rowperm[start + ml + 8];
                float mix = g_mix[r & (SEQ-1)];
                const float* mp = g_main + (size_t)r*DIM + col;
                *(float2*)(out + (size_t)r*DIM + col) =
                    make_float2(mp[0]*(1.f-mix) + (acc[mt][nt][2]+bx)*mix,
                                mp[1]*(1.f-mix) + (acc[mt][nt][3]+by)*mix);
            }
        }
    }
}

// ---------------- launch ----------------
extern "C" void kernel_launch(void* const* d_in, const int* in_sizes, int n_in,
                              void* d_out, int out_size) {
    const float* x      = (const float*)d_in[0];
    const int*   levels = (const int*)  d_in[1];
    const float* gamma  = (const float*)d_in[2];
    const float* beta   = (const float*)d_in[3];
    const float* W1     = (const float*)d_in[4];
    const float* b1     = (const float*)d_in[5];
    const float* W2     = (const float*)d_in[6];
    const float* b2     = (const float*)d_in[7];
    const float* A1     = (const float*)d_in[8];
    const float* a1b    = (const float*)d_in[9];
    const float* A2     = (const float*)d_in[10];
    const float* a2b    = (const float*)d_in[11];
    const float* lmw    = (const float*)d_in[12];
    float* out = (float*)d_out;

    cudaFuncSetAttribute(k_gemm1_main,  cudaFuncAttributeMaxDynamicSharedMemorySize, SMEM_BYTES);
    cudaFuncSetAttribute(k_mid,         cudaFuncAttributeMaxDynamicSharedMemorySize, SMEM_BYTES);
    cudaFuncSetAttribute(k_gemm2_adapt, cudaFuncAttributeMaxDynamicSharedMemorySize, A2SMEM_BYTES);

    k_prep_all<<<NB_PREP_ALL, 256>>>((const float4*)W1, (const float4*)W2,
                                     (const float4*)A1, (const float4*)A2,
                                     levels, lmw, x, gamma, beta);
    k_gemm1_main <<<dim3(NMAIN, MROWS/BM), NT, SMEM_BYTES>>>(b1);
    k_mid        <<<MID_BLKS, NT, SMEM_BYTES>>>(b2, a1b);
    k_gemm2_adapt<<<dim3(NDIM, MAX_TILES*2), NT, A2SMEM_BYTES>>>(a2b, out);
}